// round 14
// baseline (speedup 1.0000x reference)
#include <cuda_runtime.h>
#include <cuda_fp16.h>
#include <math.h>
#include <cstdint>

#define BATCH 256
#define NPATCH 256
#define CH 768
#define NATTR 10
#define NHEAD 8
#define NEXP 4
#define HD 96
#define NTOK (BATCH*NATTR)
#define SCALE 0.1020620726159658f  /* 96^-0.5 */
#define CTX_HALF ((long)BATCH*NHEAD*CH)

// ---------------- scratch (device globals; no allocations) ----------------
__device__ float g_q[BATCH*CH];
__device__ __half g_qk_h[BATCH*NHEAD*CH];       // fp16 folded qk
__device__ float g_ctx[2*BATCH*NHEAD*CH];       // split-K partial ctx (unnormalized)
__device__ float g_lsum[2*BATCH*NHEAD];         // split-K partial softmax denominators
__device__ float g_o[BATCH*CH];
__device__ float g_moe_in[BATCH*CH];
__device__ float g_wgt[NTOK*NEXP];
__device__ float g_scores[BATCH*NATTR];
__device__ float g_moe_out[(long)NTOK*CH];
__device__ float g_r2m[2];
__device__ __half g_expw_h[(long)NEXP*CH*CH];   // fp16 expert weights
__device__ __half g_attr_h[(long)NTOK*CH];      // fp16 attr (unweighted)

__device__ __forceinline__ uint32_t smem_u32(const void* p) {
    uint32_t a;
    asm("{ .reg .u64 t; cvta.to.shared.u64 t, %1; cvt.u32.u64 %0, t; }" : "=r"(a) : "l"(p));
    return a;
}

#define MMA_F16(acc, a0,a1,a2,a3, b0,b1) \
    asm volatile("mma.sync.aligned.m16n8k16.row.col.f32.f16.f16.f32 " \
        "{%0,%1,%2,%3},{%4,%5,%6,%7},{%8,%9},{%0,%1,%2,%3};" \
        : "+f"((acc)[0]), "+f"((acc)[1]), "+f"((acc)[2]), "+f"((acc)[3]) \
        : "r"(a0), "r"(a1), "r"(a2), "r"(a3), "r"(b0), "r"(b1))

#define LDSM_X4(r0,r1,r2,r3, addr) \
    asm volatile("ldmatrix.sync.aligned.m8n8.x4.shared.b16 {%0,%1,%2,%3},[%4];" \
        : "=r"(r0), "=r"(r1), "=r"(r2), "=r"(r3) : "r"(addr))

// ---------------- K0: exp_w -> fp16, last block computes r2 means ----------------
__global__ void expw_cvt_r2(const float* __restrict__ w,
                            const float* __restrict__ r2w, const float* __restrict__ r2b) {
    if (blockIdx.x == 576) {
        __shared__ float s1[256], s2[256];
        int t = threadIdx.x;
        float a = 0.f, b = 0.f;
        for (int c = t; c < CH; c += 256) { a += r2w[c]; b += r2b[c]; }
        s1[t] = a; s2[t] = b; __syncthreads();
        for (int s = 128; s > 0; s >>= 1) {
            if (t < s) { s1[t] += s1[t + s]; s2[t] += s2[t + s]; }
            __syncthreads();
        }
        if (t == 0) { g_r2m[0] = s1[0] / (float)CH; g_r2m[1] = s2[0] / (float)CH; }
        return;
    }
    const float4* src = (const float4*)w;
    uint2* dst = (uint2*)g_expw_h;
    int n4 = NEXP * CH * CH / 4;
    for (int i = blockIdx.x * 256 + threadIdx.x; i < n4; i += 576 * 256) {
        float4 v = src[i];
        __half2 h0 = __floats2half2_rn(v.x, v.y);
        __half2 h1 = __floats2half2_rn(v.z, v.w);
        dst[i] = make_uint2(*(uint32_t*)&h0, *(uint32_t*)&h1);
    }
}

// ---------------- gemm_abt_f16: C = A' @ Bm^T + bias (fp16 mma, f32 accum) ----------------
// When Asplit != 0: A' rows = (A[row] + A[row + Asplit]) * (1 / (lsum[idx] + lsum[2048+idx]))
// with idx = row * NHEAD + bz  (split-K attention reduction folded into the loader).
#define LDH 40
__global__ void __launch_bounds__(256) gemm_abt_f16(
    const float* __restrict__ A, int lda, long Asb,
    const float* __restrict__ Bm, int ldb, long Bsb,
    const float* __restrict__ bias, long biasSb,
    float* __restrict__ C, int ldc, long Csb,
    int N, int K,
    const float* __restrict__ lsum, long Asplit)
{
    __shared__ __align__(16) __half Ah[2][64 * LDH];
    __shared__ __align__(16) __half Bh[2][64 * LDH];

    int bz = blockIdx.z;
    A += (long)bz * Asb; Bm += (long)bz * Bsb; C += (long)bz * Csb;
    const float* bsp = bias + (long)bz * biasSb;

    int m0 = blockIdx.x * 64, n0 = blockIdx.y * 64;
    int tid = threadIdx.x;
    int lane = tid & 31, wid = tid >> 5;
    int wm = wid & 1, wn = wid >> 1;
    int kv = tid & 7, rw = tid >> 3;

    int gq = lane >> 3;
    uint32_t rA8 = (gq & 1) * 8 + (lane & 7), aOff = (gq >> 1) * 16;
    uint32_t rB8 = (gq >> 1) * 8 + (lane & 7), bOff = (gq & 1) * 16;
    uint32_t AhA[2] = { smem_u32(&Ah[0][0]), smem_u32(&Ah[1][0]) };
    uint32_t BhA[2] = { smem_u32(&Bh[0][0]), smem_u32(&Bh[1][0]) };

    float sA[2] = { 1.f, 1.f };
    if (lsum) {
        #pragma unroll
        for (int i = 0; i < 2; i++) {
            int idx = (m0 + rw + 32 * i) * NHEAD + bz;
            sA[i] = 1.f / (lsum[idx] + lsum[BATCH * NHEAD + idx]);
        }
    }

    float4 rA[2], rB[2];
    auto do_ldg = [&](int s) {
        int k0 = s * 32;
        #pragma unroll
        for (int i = 0; i < 2; i++) {
            int mr = rw + 32 * i;
            const float* ap = A + (long)(m0 + mr) * lda + k0 + kv * 4;
            rA[i] = *(const float4*)ap;
            if (Asplit) {
                float4 v2 = *(const float4*)(ap + Asplit);
                rA[i].x += v2.x; rA[i].y += v2.y; rA[i].z += v2.z; rA[i].w += v2.w;
            }
            int bn = n0 + mr;
            rB[i] = (bn < N) ? *(const float4*)(Bm + (long)bn * ldb + k0 + kv * 4)
                             : make_float4(0.f, 0.f, 0.f, 0.f);
        }
    };
    auto do_sts = [&](int buf) {
        #pragma unroll
        for (int i = 0; i < 2; i++) {
            int mr = rw + 32 * i;
            __half2 a0 = __floats2half2_rn(rA[i].x * sA[i], rA[i].y * sA[i]);
            __half2 a1 = __floats2half2_rn(rA[i].z * sA[i], rA[i].w * sA[i]);
            *(__half2*)&Ah[buf][mr * LDH + kv * 4]     = a0;
            *(__half2*)&Ah[buf][mr * LDH + kv * 4 + 2] = a1;
            __half2 b0 = __floats2half2_rn(rB[i].x, rB[i].y);
            __half2 b1 = __floats2half2_rn(rB[i].z, rB[i].w);
            *(__half2*)&Bh[buf][mr * LDH + kv * 4]     = b0;
            *(__half2*)&Bh[buf][mr * LDH + kv * 4 + 2] = b1;
        }
    };

    do_ldg(0);
    do_sts(0);
    do_ldg(1);
    __syncthreads();

    int lr = lane >> 2, lc = lane & 3;
    int nsteps = K / 32;
    float acc[2][2][4] = {};
    for (int s = 0; s < nsteps; s++) {
        int buf = s & 1;
        #pragma unroll
        for (int kk = 0; kk < 2; kk++) {
            uint32_t af[2][4];
            #pragma unroll
            for (int mi = 0; mi < 2; mi++)
                LDSM_X4(af[mi][0], af[mi][1], af[mi][2], af[mi][3],
                        AhA[buf] + (wm * 32 + mi * 16 + rA8) * 80 + kk * 32 + aOff);
            uint32_t b0, b1, b2, b3;
            LDSM_X4(b0, b1, b2, b3,
                    BhA[buf] + (wn * 16 + rB8) * 80 + kk * 32 + bOff);
            #pragma unroll
            for (int mi = 0; mi < 2; mi++) {
                MMA_F16(acc[mi][0], af[mi][0], af[mi][1], af[mi][2], af[mi][3], b0, b1);
                MMA_F16(acc[mi][1], af[mi][0], af[mi][1], af[mi][2], af[mi][3], b2, b3);
            }
        }
        if (s < nsteps - 1) do_sts(buf ^ 1);
        if (s < nsteps - 2) do_ldg(s + 2);
        __syncthreads();
    }

    #pragma unroll
    for (int mi = 0; mi < 2; mi++) {
        int r = m0 + wm * 32 + mi * 16 + lr;
        #pragma unroll
        for (int ni = 0; ni < 2; ni++) {
            int c = n0 + wn * 16 + ni * 8 + lc * 2;
            if (c < N) {
                float b0v = bsp[c], b1v = bsp[c + 1];
                *(float2*)(C + (long)r * ldc + c) =
                    make_float2(acc[mi][ni][0] + b0v, acc[mi][ni][1] + b1v);
                *(float2*)(C + (long)(r + 8) * ldc + c) =
                    make_float2(acc[mi][ni][2] + b0v, acc[mi][ni][3] + b1v);
            }
        }
    }
}

// ---------------- gemm_ab_f16: C = scale * (A @ B) -> fp16  (qk fold) ----------------
#define QK_LDA2 52
#define QK_LDB2 36
__global__ void __launch_bounds__(256) gemm_ab_f16(
    const float* __restrict__ A, int lda, long Asb,
    const float* __restrict__ B, int ldb, long BsbRows,
    __half* __restrict__ C, int ldc, long Csb, float scale)
{
    __shared__ __align__(16) uint32_t Ash[64 * QK_LDA2];
    __shared__ __align__(16) uint32_t Bsh[96 * QK_LDB2];

    int h = blockIdx.z;
    A += (long)h * Asb;
    B += (long)h * BsbRows * ldb;
    C += (long)h * Csb;

    int m0 = blockIdx.x * 64, n0 = blockIdx.y * 64;
    int tid = threadIdx.x;
    int lane = tid & 31, wid = tid >> 5;
    int wm = wid & 1, wn = wid >> 1;
    int lr = lane >> 2, lc = lane & 3;
    int gq = lane >> 3;
    uint32_t rA8 = (gq & 1) * 8 + (lane & 7), aOff = (gq >> 1) * 16;

    #pragma unroll
    for (int it = 0; it < 6; it++) {
        int idx = tid + 256 * it;
        int row = idx / 24, c4 = idx % 24;
        float4 v = *(const float4*)(A + (long)(m0 + row) * lda + c4 * 4);
        __half2 h0 = __floats2half2_rn(v.x, v.y);
        __half2 h1 = __floats2half2_rn(v.z, v.w);
        *(uint2*)(Ash + row * QK_LDA2 + c4 * 2) = make_uint2(*(uint32_t*)&h0, *(uint32_t*)&h1);
    }
    #pragma unroll
    for (int it = 0; it < 6; it++) {
        int idx = tid + 256 * it;
        int row = idx >> 4, c4 = idx & 15;
        float4 v = *(const float4*)(B + (long)row * ldb + n0 + c4 * 4);
        __half2 h0 = __floats2half2_rn(v.x, v.y);
        __half2 h1 = __floats2half2_rn(v.z, v.w);
        *(uint2*)(Bsh + row * QK_LDB2 + c4 * 2) = make_uint2(*(uint32_t*)&h0, *(uint32_t*)&h1);
    }
    __syncthreads();

    uint32_t aBase = smem_u32(Ash);
    uint32_t bBase = smem_u32(Bsh);
    float acc[2][2][4] = {};
    #pragma unroll
    for (int ks = 0; ks < 6; ks++) {
        uint32_t af[2][4];
        #pragma unroll
        for (int mi = 0; mi < 2; mi++)
            LDSM_X4(af[mi][0], af[mi][1], af[mi][2], af[mi][3],
                    aBase + (wm * 32 + mi * 16 + rA8) * 208 + ks * 32 + aOff);
        uint32_t rowAddr = bBase + (uint32_t)((ks * 16 + (lane & 15)) * (QK_LDB2 * 4));
        #pragma unroll
        for (int ni = 0; ni < 2; ni++) {
            int cb = (wn * 16 + ni * 8) * 2;
            uint32_t b0, b1;
            asm volatile("ldmatrix.sync.aligned.m8n8.x2.trans.shared.b16 {%0,%1},[%2];"
                         : "=r"(b0), "=r"(b1) : "r"(rowAddr + cb));
            #pragma unroll
            for (int mi = 0; mi < 2; mi++)
                MMA_F16(acc[mi][ni], af[mi][0], af[mi][1], af[mi][2], af[mi][3], b0, b1);
        }
    }

    #pragma unroll
    for (int mi = 0; mi < 2; mi++) {
        int r = m0 + wm * 32 + mi * 16 + lr;
        #pragma unroll
        for (int ni = 0; ni < 2; ni++) {
            int c = n0 + wn * 16 + ni * 8 + lc * 2;
            *(__half2*)(C + (long)r * ldc + c) =
                __floats2half2_rn(acc[mi][ni][0] * scale, acc[mi][ni][1] * scale);
            *(__half2*)(C + (long)(r + 8) * ldc + c) =
                __floats2half2_rn(acc[mi][ni][2] * scale, acc[mi][ni][3] * scale);
        }
    }
}

// ---------------- K3: attention, split-K over patches (2 CTAs/batch) ----------------
#define ATT_QKH 0
#define ATT_PN0 24832
#define ATT_PN1 49664
#define ATT_RED 74496
#define ATT_PROB 78592
#define ATT_LS  79424
#define ATT_QB  79552
#define ATTN_SMEM 79616

__global__ void __launch_bounds__(256, 2) attn_mma_kernel(
    const float* __restrict__ patches, const float* __restrict__ bk)
{
    extern __shared__ char sm[];
    uint32_t* qkhU = (uint32_t*)(sm + ATT_QKH);
    float* redS = (float*)(sm + ATT_RED);
    uint32_t* phU = (uint32_t*)(sm + ATT_PROB);
    float* lS = (float*)(sm + ATT_LS);
    float* qbS = (float*)(sm + ATT_QB);

    int b = blockIdx.x, half = blockIdx.y, tid = threadIdx.x;
    int lane = tid & 31, wid = tid >> 5;
    int lr = lane >> 2, lc = lane & 3;
    uint32_t smBase = smem_u32(sm);
    int gq = lane >> 3;
    uint32_t rA8 = (gq & 1) * 8 + (lane & 7), aOff = (gq >> 1) * 16;
    uint32_t rB8 = (gq >> 1) * 8 + (lane & 7), bOff = (gq & 1) * 16;

    {
        const uint4* qsrc = (const uint4*)(g_qk_h + (long)b * NHEAD * CH);
        #pragma unroll
        for (int j = 0; j < 3; j++) {
            int f = tid + 256 * j;
            int r = f / 96, c16 = f % 96;
            *(uint4*)(qkhU + r * 388 + c16 * 4) = qsrc[f];
        }
        for (int i = tid; i < 8 * 388; i += 256) qkhU[8 * 388 + i] = 0;
        for (int i = tid; i < 192; i += 256) phU[i] = 0;
        if (tid < 8) lS[tid] = 0.f;
        float s = 0.f;
        #pragma unroll
        for (int j = 0; j < 3; j++) {
            int d = lane + 32 * j;
            s += g_q[b * CH + wid * HD + d] * bk[wid * HD + d];
        }
        #pragma unroll
        for (int o = 16; o > 0; o >>= 1) s += __shfl_xor_sync(0xffffffffu, s, o);
        if (lane == 0) qbS[wid] = s * SCALE;
    }

    int lrow = tid >> 4, lcol = tid & 15;
    const float4* pb4 = (const float4*)(patches + ((long)b * NPATCH + half * 128) * CH);
    uint32_t stg[24];

    auto ldg_tile = [&](int t) {
        const float4* src = pb4 + (long)(16 * t + lrow) * 192 + lcol;
        #pragma unroll
        for (int j = 0; j < 12; j++) {
            float4 v = src[16 * j];
            __half2 h0 = __floats2half2_rn(v.x, v.y);
            __half2 h1 = __floats2half2_rn(v.z, v.w);
            stg[2 * j] = *(uint32_t*)&h0; stg[2 * j + 1] = *(uint32_t*)&h1;
        }
    };
    auto sts_tile = [&](int buf) {
        uint32_t* dst = (uint32_t*)(sm + (buf ? ATT_PN1 : ATT_PN0)) + lrow * 388 + lcol * 2;
        #pragma unroll
        for (int j = 0; j < 12; j++)
            *(uint2*)(dst + 32 * j) = make_uint2(stg[2 * j], stg[2 * j + 1]);
    };

    ldg_tile(0);
    sts_tile(0);
    __syncthreads();

    float ctx[12][4] = {};
    uint32_t qkhAddr = smBase + ATT_QKH;
    uint32_t kwB = wid * 192;

    for (int t = 0; t < 8; t++) {
        int buf = t & 1;
        uint32_t pnAddr = smBase + (buf ? ATT_PN1 : ATT_PN0);

        if (t < 7) ldg_tile(t + 1);

        float lgC[2][4] = {};
        #pragma unroll
        for (int ks = 0; ks < 6; ks++) {
            uint32_t a0, a1, a2, a3;
            LDSM_X4(a0, a1, a2, a3, qkhAddr + rA8 * 1552 + kwB + ks * 32 + aOff);
            uint32_t b0, b1, b2, b3;
            LDSM_X4(b0, b1, b2, b3, pnAddr + rB8 * 1552 + kwB + ks * 32 + bOff);
            MMA_F16(lgC[0], a0, a1, a2, a3, b0, b1);
            MMA_F16(lgC[1], a0, a1, a2, a3, b2, b3);
        }
        {
            float* rw = redS + wid * 128;
            #pragma unroll
            for (int nc = 0; nc < 2; nc++)
                *(float2*)(rw + lr * 16 + nc * 8 + 2 * lc) = make_float2(lgC[nc][0], lgC[nc][1]);
        }
        __syncthreads();

        // non-safe softmax: p = exp(lg) directly (|lg| <= ~3 for this model)
        if (tid < 128) {
            int h = tid >> 4, n = tid & 15;
            float lg = qbS[h];
            #pragma unroll
            for (int w = 0; w < 8; w++) lg += redS[w * 128 + h * 16 + n];
            float p = __expf(lg);
            float ps = p;
            #pragma unroll
            for (int o = 8; o > 0; o >>= 1) ps += __shfl_xor_sync(0xffffffffu, ps, o);
            if (n == 0) lS[h] += ps;
            ((__half*)phU)[h * 24 + n] = __float2half(p);
        }
        __syncthreads();

        {
            uint32_t pa0 = phU[lr * 12 + lc];
            uint32_t pa1 = phU[(lr + 8) * 12 + lc];
            uint32_t pa2 = phU[lr * 12 + lc + 4];
            uint32_t pa3 = phU[(lr + 8) * 12 + lc + 4];
            uint32_t rowAddr = pnAddr + (lane & 15) * 1552;
            #pragma unroll
            for (int j = 0; j < 12; j++) {
                int ch = wid * 96 + 8 * j;
                uint32_t b0, b1;
                asm volatile("ldmatrix.sync.aligned.m8n8.x2.trans.shared.b16 {%0,%1},[%2];"
                             : "=r"(b0), "=r"(b1) : "r"(rowAddr + ch * 2));
                MMA_F16(ctx[j], pa0, pa1, pa2, pa3, b0, b1);
            }
        }
        if (t < 7) sts_tile(buf ^ 1);
        __syncthreads();
    }

    // epilogue: write unnormalized partials (reduction happens in the Wv GEMM loader)
    {
        float* dst = g_ctx + (long)half * CTX_HALF + ((long)b * 8 + lr) * CH;
        #pragma unroll
        for (int j = 0; j < 12; j++) {
            int ch = wid * 96 + 8 * j + 2 * lc;
            *(float2*)(dst + ch) = make_float2(ctx[j][0], ctx[j][1]);
        }
        if (tid < 8) g_lsum[half * BATCH * NHEAD + b * 8 + tid] = lS[tid];
    }
}

// ---------------- K5: attr_in + gating + router, warp per token ----------------
__global__ void __launch_bounds__(256) attr_gate_warp(
    const float* __restrict__ prompt, const float* __restrict__ vcls,
    const float* __restrict__ gate_w, const float* __restrict__ gate_b,
    const float* __restrict__ r1_w, const float* __restrict__ r1_b)
{
    int warp = (blockIdx.x * 256 + threadIdx.x) >> 5;
    int lane = threadIdx.x & 31;
    int b = warp / NATTR, a = warp % NATTR;

    float x[24];
    float part[5] = {};
    #pragma unroll
    for (int j = 0; j < 12; j++) {
        int c = lane * 2 + 64 * j;
        float2 mi = *(const float2*)&g_moe_in[b * CH + c];
        float2 pr = *(const float2*)&prompt[a * CH + c];
        float2 vc = *(const float2*)&vcls[b * CH + c];
        float x0 = mi.x + pr.x + vc.x;
        float x1 = mi.y + pr.y + vc.y;
        x[2 * j] = x0; x[2 * j + 1] = x1;
        #pragma unroll
        for (int e = 0; e < 4; e++) {
            float2 gw = *(const float2*)&gate_w[e * CH + c];
            part[e] += x0 * gw.x + x1 * gw.y;
        }
        float2 r1 = *(const float2*)&r1_w[c];
        part[4] += x0 * r1.x + x1 * r1.y;
    }
    #pragma unroll
    for (int o = 16; o > 0; o >>= 1)
        #pragma unroll
        for (int e = 0; e < 5; e++) part[e] += __shfl_xor_sync(0xffffffffu, part[e], o);

    float g[4];
    #pragma unroll
    for (int e = 0; e < 4; e++) g[e] = part[e] + gate_b[e];
    float v0 = g[0], v1 = g[1], v2 = g[2], v3 = g[3], t;
    if (v0 < v1) { t = v0; v0 = v1; v1 = t; }
    if (v2 < v3) { t = v2; v2 = v3; v3 = t; }
    if (v0 < v2) { t = v0; v0 = v2; v2 = t; }
    if (v1 < v3) { t = v1; v1 = v3; v3 = t; }
    if (v1 < v2) { t = v1; v1 = v2; v2 = t; }
    float thr = v2, mx = v0;
    float s = 0.f, w[4];
    #pragma unroll
    for (int e = 0; e < 4; e++) {
        w[e] = (g[e] >= thr) ? __expf(g[e] - mx) : 0.f;
        s += w[e];
    }
    float inv = 1.f / s;
    if (lane == 0) {
        *(float4*)&g_wgt[warp * 4] = make_float4(w[0] * inv, w[1] * inv, w[2] * inv, w[3] * inv);
        float hv = part[4] + r1_b[0];
        float x3 = hv * hv * hv;
        float gl = 0.5f * hv * (1.f + tanhf(0.7978845608028654f * (hv + 0.044715f * x3)));
        g_scores[warp] = gl * g_r2m[0] + g_r2m[1];
    }

    __half* dst = g_attr_h + (long)warp * CH;
    #pragma unroll
    for (int j = 0; j < 12; j++) {
        int c = lane * 2 + 64 * j;
        *(__half2*)&dst[c] = __floats2half2_rn(x[2 * j], x[2 * j + 1]);
    }
}

// ---------------- K6: expert GEMM, 64x128 tiles (grid 40x6 = 240 CTAs) ----------------
__global__ void __launch_bounds__(256) expert_fp16_kernel(const float* __restrict__ exp_b) {
    __shared__ float ebS[512];
    __shared__ float wS[256];
    __shared__ __align__(16) __half Ah[2][64 * LDH];
    __shared__ __align__(16) __half Bh[2][128 * LDH];

    int m0c = blockIdx.x * 64, n0c = blockIdx.y * 128;
    int tid = threadIdx.x;
    int lane = tid & 31, wid = tid >> 5;
    int wm = wid & 1, wn = wid >> 1;          // warp tile 32(m) x 32(n)
    int kv = tid & 3, rb = tid >> 2;          // loader: 64 rows x 4 uint4

    int gq = lane >> 3;
    uint32_t rA8 = (gq & 1) * 8 + (lane & 7), aOff = (gq >> 1) * 16;
    uint32_t rB8 = (gq >> 1) * 8 + (lane & 7), bOff = (gq & 1) * 16;
    uint32_t AhA[2] = { smem_u32(&Ah[0][0]), smem_u32(&Ah[1][0]) };
    uint32_t BhA[2] = { smem_u32(&Bh[0][0]), smem_u32(&Bh[1][0]) };

    for (int i = tid; i < 512; i += 256)
        ebS[i] = exp_b[(i >> 7) * CH + n0c + (i & 127)];
    if (tid < 256)
        wS[tid] = g_wgt[(m0c + (tid >> 2)) * 4 + (tid & 3)];

    uint4 uA, uB[2];
    auto do_ldg = [&](int s) {
        int e = s / 24, k0 = (s % 24) * 32;
        uA = *(const uint4*)(g_attr_h + (long)(m0c + rb) * CH + k0 + kv * 8);
        const __half* bp = g_expw_h + (long)e * CH * CH + (long)(n0c + rb) * CH + k0 + kv * 8;
        uB[0] = *(const uint4*)bp;
        uB[1] = *(const uint4*)(bp + (long)64 * CH);
    };
    auto do_sts = [&](int buf, int e) {
        __half2 hw = __float2half2_rn(wS[rb * 4 + e]);
        uint4 u = uA;
        __half2* h2 = (__half2*)&u;
        h2[0] = __hmul2(h2[0], hw); h2[1] = __hmul2(h2[1], hw);
        h2[2] = __hmul2(h2[2], hw); h2[3] = __hmul2(h2[3], hw);
        *(uint4*)&Ah[buf][rb * LDH + kv * 8] = u;
        *(uint4*)&Bh[buf][rb * LDH + kv * 8] = uB[0];
        *(uint4*)&Bh[buf][(rb + 64) * LDH + kv * 8] = uB[1];
    };

    do_ldg(0);
    __syncthreads();            // wS ready
    do_sts(0, 0);
    do_ldg(1);
    __syncthreads();

    int lr = lane >> 2, lc = lane & 3;
    float acc[2][4][4] = {};
    for (int s = 0; s < 96; s++) {
        int buf = s & 1;
        #pragma unroll
        for (int kk = 0; kk < 2; kk++) {
            uint32_t af[2][4];
            #pragma unroll
            for (int mi = 0; mi < 2; mi++)
                LDSM_X4(af[mi][0], af[mi][1], af[mi][2], af[mi][3],
                        AhA[buf] + (wm * 32 + mi * 16 + rA8) * 80 + kk * 32 + aOff);
            uint32_t bf[4][2];
            #pragma unroll
            for (int p = 0; p < 2; p++)
                LDSM_X4(bf[2 * p][0], bf[2 * p][1], bf[2 * p + 1][0], bf[2 * p + 1][1],
                        BhA[buf] + (wn * 32 + p * 16 + rB8) * 80 + kk * 32 + bOff);
            #pragma unroll
            for (int mi = 0; mi < 2; mi++)
                #pragma unroll
                for (int ni = 0; ni < 4; ni++)
                    MMA_F16(acc[mi][ni], af[mi][0], af[mi][1], af[mi][2], af[mi][3],
                            bf[ni][0], bf[ni][1]);
        }
        if (s < 95) do_sts(buf ^ 1, (s + 1) / 24);
        if (s < 94) do_ldg(s + 2);
        __syncthreads();
    }

    #pragma unroll
    for (int mi = 0; mi < 2; mi++) {
        int r0 = wm * 32 + mi * 16 + lr;
        float4 w0 = *(const float4*)&wS[r0 * 4];
        float4 w1 = *(const float4*)&wS[(r0 + 8) * 4];
        #pragma unroll
        for (int ni = 0; ni < 4; ni++) {
            int c = wn * 32 + ni * 8 + lc * 2;
            float e0 = ebS[c],       f0 = ebS[c + 1];
            float e1 = ebS[128 + c], f1 = ebS[129 + c];
            float e2 = ebS[256 + c], f2 = ebS[257 + c];
            float e3 = ebS[384 + c], f3 = ebS[385 + c];
            float b00 = w0.x * e0 + w0.y * e1 + w0.z * e2 + w0.w * e3;
            float b01 = w0.x * f0 + w0.y * f1 + w0.z * f2 + w0.w * f3;
            float b10 = w1.x * e0 + w1.y * e1 + w1.z * e2 + w1.w * e3;
            float b11 = w1.x * f0 + w1.y * f1 + w1.z * f2 + w1.w * f3;
            *(float2*)(g_moe_out + (size_t)(m0c + r0) * CH + n0c + c) =
                make_float2(acc[mi][ni][0] + b00, acc[mi][ni][1] + b01);
            *(float2*)(g_moe_out + (size_t)(m0c + r0 + 8) * CH + n0c + c) =
                make_float2(acc[mi][ni][2] + b10, acc[mi][ni][3] + b11);
        }
    }
}

// ---------------- K7: top-7-of-10 attrs, softmax combine ----------------
__global__ void final_kernel(float* __restrict__ out) {
    int b = blockIdx.x, tid = threadIdx.x;
    __shared__ float wts[7];
    __shared__ int idx[7];
    if (tid == 0) {
        float sc[10];
        for (int a = 0; a < 10; a++) sc[a] = g_scores[b * 10 + a];
        bool used[10] = {};
        float vs[7];
        for (int k = 0; k < 7; k++) {
            int bi = 0; float bv = -3.4e38f;
            for (int a = 0; a < 10; a++) {
                if (!used[a] && sc[a] > bv) { bv = sc[a]; bi = a; }
            }
            used[bi] = true; vs[k] = bv; idx[k] = bi;
        }
        float mx = vs[0], s = 0.f;
        for (int k = 0; k < 7; k++) { vs[k] = __expf(vs[k] - mx); s += vs[k]; }
        float inv = 1.f / s;
        for (int k = 0; k < 7; k++) wts[k] = vs[k] * inv;
    }
    __syncthreads();
    #pragma unroll
    for (int j = 0; j < 3; j++) {
        int c = tid + j * 256;
        float s = 0.f;
        #pragma unroll
        for (int k = 0; k < 7; k++)
            s += wts[k] * g_moe_out[((long)b * 10 + idx[k]) * CH + c];
        out[b * CH + c] = s;
    }
}

// ---------------- host ----------------
extern "C" void kernel_launch(void* const* d_in, const int* in_sizes, int n_in,
                              void* d_out, int out_size) {
    const float* text_cls = (const float*)d_in[0];
    const float* visual_cls = (const float*)d_in[1];
    const float* patches = (const float*)d_in[2];
    const float* prompt = (const float*)d_in[3];
    const float* Wq = (const float*)d_in[4];  const float* bq = (const float*)d_in[5];
    const float* Wk = (const float*)d_in[6];  const float* bk = (const float*)d_in[7];
    const float* Wv = (const float*)d_in[8];  const float* bv = (const float*)d_in[9];
    const float* Wo = (const float*)d_in[10]; const float* bo = (const float*)d_in[11];
    const float* gate_w = (const float*)d_in[12]; const float* gate_b = (const float*)d_in[13];
    const float* exp_w = (const float*)d_in[14];  const float* exp_b = (const float*)d_in[15];
    const float* r1_w = (const float*)d_in[16];   const float* r1_b = (const float*)d_in[17];
    const float* r2_w = (const float*)d_in[18];   const float* r2_b = (const float*)d_in[19];
    float* out = (float*)d_out;

    (void)in_sizes; (void)n_in; (void)out_size;

    float *p_q, *p_ctx, *p_o, *p_moe_in, *p_lsum;
    __half* p_qkh;
    cudaGetSymbolAddress((void**)&p_q, g_q);
    cudaGetSymbolAddress((void**)&p_qkh, g_qk_h);
    cudaGetSymbolAddress((void**)&p_ctx, g_ctx);
    cudaGetSymbolAddress((void**)&p_lsum, g_lsum);
    cudaGetSymbolAddress((void**)&p_o, g_o);
    cudaGetSymbolAddress((void**)&p_moe_in, g_moe_in);

    cudaFuncSetAttribute(attn_mma_kernel, cudaFuncAttributeMaxDynamicSharedMemorySize, ATTN_SMEM);

    expw_cvt_r2<<<577, 256>>>(exp_w, r2_w, r2_b);
    // q = text_cls @ Wq^T + bq
    gemm_abt_f16<<<dim3(4, 12, 1), 256>>>(text_cls, CH, 0, Wq, CH, 0, bq, 0,
                                          p_q, CH, 0, CH, CH, nullptr, 0);
    // qk fold (fp16 out): per head h, qk_h = SCALE * (q_h @ Wk[h*96:(h+1)*96, :])
    gemm_ab_f16<<<dim3(4, 12, 8), 256>>>(p_q, CH, HD,
                                         Wk, CH, HD,
                                         p_qkh, NHEAD * CH, CH, SCALE);
    // split-K attention: 2 CTAs per batch, unnormalized partials
    attn_mma_kernel<<<dim3(BATCH, 2), 256, ATTN_SMEM>>>(patches, bk);
    // o slice: (ctx_raw0+ctx_raw1)/l @ Wv_h^T + bv_h  (reduction in loader)
    gemm_abt_f16<<<dim3(4, 2, 8), 256>>>(p_ctx, NHEAD * CH, CH,
                                         Wv, CH, (long)HD * CH,
                                         bv, HD,
                                         p_o, CH, HD, HD, CH,
                                         p_lsum, CTX_HALF);
    // moe_in = o @ Wo^T + bo
    gemm_abt_f16<<<dim3(4, 12, 1), 256>>>(p_o, CH, 0, Wo, CH, 0, bo, 0,
                                          p_moe_in, CH, 0, CH, CH, nullptr, 0);
    attr_gate_warp<<<320, 256>>>(prompt, visual_cls, gate_w, gate_b, r1_w, r1_b);
    expert_fp16_kernel<<<dim3(40, 6), 256>>>(exp_b);
    final_kernel<<<BATCH, 256>>>(out);
}

// round 15
// speedup vs baseline: 1.1704x; 1.1704x over previous
#include <cuda_runtime.h>
#include <cuda_fp16.h>
#include <math.h>
#include <cstdint>

#define BATCH 256
#define NPATCH 256
#define CH 768
#define NATTR 10
#define NHEAD 8
#define NEXP 4
#define HD 96
#define NTOK (BATCH*NATTR)
#define SCALE 0.1020620726159658f  /* 96^-0.5 */

// ---------------- scratch (device globals; no allocations) ----------------
__device__ float g_q[BATCH*CH];
__device__ __half g_qk_h[BATCH*NHEAD*CH];       // fp16 folded qk
__device__ float g_ctx[BATCH*NHEAD*CH];
__device__ float g_o[BATCH*CH];
__device__ float g_moe_in[BATCH*CH];
__device__ float g_wgt[NTOK*NEXP];
__device__ float g_scores[BATCH*NATTR];
__device__ float g_moe_out[2*(long)NTOK*CH];    // two expert-group partials
__device__ float g_r2m[2];
__device__ __half g_expw_h[(long)NEXP*CH*CH];   // fp16 expert weights
__device__ __half g_attr_h[(long)NTOK*CH];      // fp16 attr (unweighted)

__device__ __forceinline__ uint32_t smem_u32(const void* p) {
    uint32_t a;
    asm("{ .reg .u64 t; cvta.to.shared.u64 t, %1; cvt.u32.u64 %0, t; }" : "=r"(a) : "l"(p));
    return a;
}

#define MMA_F16(acc, a0,a1,a2,a3, b0,b1) \
    asm volatile("mma.sync.aligned.m16n8k16.row.col.f32.f16.f16.f32 " \
        "{%0,%1,%2,%3},{%4,%5,%6,%7},{%8,%9},{%0,%1,%2,%3};" \
        : "+f"((acc)[0]), "+f"((acc)[1]), "+f"((acc)[2]), "+f"((acc)[3]) \
        : "r"(a0), "r"(a1), "r"(a2), "r"(a3), "r"(b0), "r"(b1))

#define LDSM_X4(r0,r1,r2,r3, addr) \
    asm volatile("ldmatrix.sync.aligned.m8n8.x4.shared.b16 {%0,%1,%2,%3},[%4];" \
        : "=r"(r0), "=r"(r1), "=r"(r2), "=r"(r3) : "r"(addr))

// ---------------- K0: exp_w -> fp16, last block computes r2 means ----------------
__global__ void expw_cvt_r2(const float* __restrict__ w,
                            const float* __restrict__ r2w, const float* __restrict__ r2b) {
    if (blockIdx.x == 576) {
        __shared__ float s1[256], s2[256];
        int t = threadIdx.x;
        float a = 0.f, b = 0.f;
        for (int c = t; c < CH; c += 256) { a += r2w[c]; b += r2b[c]; }
        s1[t] = a; s2[t] = b; __syncthreads();
        for (int s = 128; s > 0; s >>= 1) {
            if (t < s) { s1[t] += s1[t + s]; s2[t] += s2[t + s]; }
            __syncthreads();
        }
        if (t == 0) { g_r2m[0] = s1[0] / (float)CH; g_r2m[1] = s2[0] / (float)CH; }
        return;
    }
    const float4* src = (const float4*)w;
    uint2* dst = (uint2*)g_expw_h;
    int n4 = NEXP * CH * CH / 4;
    for (int i = blockIdx.x * 256 + threadIdx.x; i < n4; i += 576 * 256) {
        float4 v = src[i];
        __half2 h0 = __floats2half2_rn(v.x, v.y);
        __half2 h1 = __floats2half2_rn(v.z, v.w);
        dst[i] = make_uint2(*(uint32_t*)&h0, *(uint32_t*)&h1);
    }
}

// ---------------- gemm_abt_f16: C = A @ Bm^T + bias (fp16 mma, f32 accum) ----------------
#define LDH 40
__global__ void __launch_bounds__(256) gemm_abt_f16(
    const float* __restrict__ A, int lda, long Asb,
    const float* __restrict__ Bm, int ldb, long Bsb,
    const float* __restrict__ bias, long biasSb,
    float* __restrict__ C, int ldc, long Csb,
    int N, int K)
{
    __shared__ __align__(16) __half Ah[2][64 * LDH];
    __shared__ __align__(16) __half Bh[2][64 * LDH];

    int bz = blockIdx.z;
    A += (long)bz * Asb; Bm += (long)bz * Bsb; C += (long)bz * Csb;
    const float* bsp = bias + (long)bz * biasSb;

    int m0 = blockIdx.x * 64, n0 = blockIdx.y * 64;
    int tid = threadIdx.x;
    int lane = tid & 31, wid = tid >> 5;
    int wm = wid & 1, wn = wid >> 1;
    int kv = tid & 7, rw = tid >> 3;

    int gq = lane >> 3;
    uint32_t rA8 = (gq & 1) * 8 + (lane & 7), aOff = (gq >> 1) * 16;
    uint32_t rB8 = (gq >> 1) * 8 + (lane & 7), bOff = (gq & 1) * 16;
    uint32_t AhA[2] = { smem_u32(&Ah[0][0]), smem_u32(&Ah[1][0]) };
    uint32_t BhA[2] = { smem_u32(&Bh[0][0]), smem_u32(&Bh[1][0]) };

    float4 rA[2], rB[2];
    auto do_ldg = [&](int s) {
        int k0 = s * 32;
        #pragma unroll
        for (int i = 0; i < 2; i++) {
            int mr = rw + 32 * i;
            rA[i] = *(const float4*)(A + (long)(m0 + mr) * lda + k0 + kv * 4);
            int bn = n0 + mr;
            rB[i] = (bn < N) ? *(const float4*)(Bm + (long)bn * ldb + k0 + kv * 4)
                             : make_float4(0.f, 0.f, 0.f, 0.f);
        }
    };
    auto do_sts = [&](int buf) {
        #pragma unroll
        for (int i = 0; i < 2; i++) {
            int mr = rw + 32 * i;
            __half2 a0 = __floats2half2_rn(rA[i].x, rA[i].y);
            __half2 a1 = __floats2half2_rn(rA[i].z, rA[i].w);
            *(__half2*)&Ah[buf][mr * LDH + kv * 4]     = a0;
            *(__half2*)&Ah[buf][mr * LDH + kv * 4 + 2] = a1;
            __half2 b0 = __floats2half2_rn(rB[i].x, rB[i].y);
            __half2 b1 = __floats2half2_rn(rB[i].z, rB[i].w);
            *(__half2*)&Bh[buf][mr * LDH + kv * 4]     = b0;
            *(__half2*)&Bh[buf][mr * LDH + kv * 4 + 2] = b1;
        }
    };

    do_ldg(0);
    do_sts(0);
    do_ldg(1);
    __syncthreads();

    int lr = lane >> 2, lc = lane & 3;
    int nsteps = K / 32;
    float acc[2][2][4] = {};
    for (int s = 0; s < nsteps; s++) {
        int buf = s & 1;
        #pragma unroll
        for (int kk = 0; kk < 2; kk++) {
            uint32_t af[2][4];
            #pragma unroll
            for (int mi = 0; mi < 2; mi++)
                LDSM_X4(af[mi][0], af[mi][1], af[mi][2], af[mi][3],
                        AhA[buf] + (wm * 32 + mi * 16 + rA8) * 80 + kk * 32 + aOff);
            uint32_t b0, b1, b2, b3;
            LDSM_X4(b0, b1, b2, b3,
                    BhA[buf] + (wn * 16 + rB8) * 80 + kk * 32 + bOff);
            #pragma unroll
            for (int mi = 0; mi < 2; mi++) {
                MMA_F16(acc[mi][0], af[mi][0], af[mi][1], af[mi][2], af[mi][3], b0, b1);
                MMA_F16(acc[mi][1], af[mi][0], af[mi][1], af[mi][2], af[mi][3], b2, b3);
            }
        }
        if (s < nsteps - 1) do_sts(buf ^ 1);
        if (s < nsteps - 2) do_ldg(s + 2);
        __syncthreads();
    }

    #pragma unroll
    for (int mi = 0; mi < 2; mi++) {
        int r = m0 + wm * 32 + mi * 16 + lr;
        #pragma unroll
        for (int ni = 0; ni < 2; ni++) {
            int c = n0 + wn * 16 + ni * 8 + lc * 2;
            if (c < N) {
                float b0v = bsp[c], b1v = bsp[c + 1];
                *(float2*)(C + (long)r * ldc + c) =
                    make_float2(acc[mi][ni][0] + b0v, acc[mi][ni][1] + b1v);
                *(float2*)(C + (long)(r + 8) * ldc + c) =
                    make_float2(acc[mi][ni][2] + b0v, acc[mi][ni][3] + b1v);
            }
        }
    }
}

// ---------------- gemm_ab_f16: C = scale * (A @ B) -> fp16  (qk fold) ----------------
#define QK_LDA2 52
#define QK_LDB2 36
__global__ void __launch_bounds__(256) gemm_ab_f16(
    const float* __restrict__ A, int lda, long Asb,
    const float* __restrict__ B, int ldb, long BsbRows,
    __half* __restrict__ C, int ldc, long Csb, float scale)
{
    __shared__ __align__(16) uint32_t Ash[64 * QK_LDA2];
    __shared__ __align__(16) uint32_t Bsh[96 * QK_LDB2];

    int h = blockIdx.z;
    A += (long)h * Asb;
    B += (long)h * BsbRows * ldb;
    C += (long)h * Csb;

    int m0 = blockIdx.x * 64, n0 = blockIdx.y * 64;
    int tid = threadIdx.x;
    int lane = tid & 31, wid = tid >> 5;
    int wm = wid & 1, wn = wid >> 1;
    int lr = lane >> 2, lc = lane & 3;
    int gq = lane >> 3;
    uint32_t rA8 = (gq & 1) * 8 + (lane & 7), aOff = (gq >> 1) * 16;

    #pragma unroll
    for (int it = 0; it < 6; it++) {
        int idx = tid + 256 * it;
        int row = idx / 24, c4 = idx % 24;
        float4 v = *(const float4*)(A + (long)(m0 + row) * lda + c4 * 4);
        __half2 h0 = __floats2half2_rn(v.x, v.y);
        __half2 h1 = __floats2half2_rn(v.z, v.w);
        *(uint2*)(Ash + row * QK_LDA2 + c4 * 2) = make_uint2(*(uint32_t*)&h0, *(uint32_t*)&h1);
    }
    #pragma unroll
    for (int it = 0; it < 6; it++) {
        int idx = tid + 256 * it;
        int row = idx >> 4, c4 = idx & 15;
        float4 v = *(const float4*)(B + (long)row * ldb + n0 + c4 * 4);
        __half2 h0 = __floats2half2_rn(v.x, v.y);
        __half2 h1 = __floats2half2_rn(v.z, v.w);
        *(uint2*)(Bsh + row * QK_LDB2 + c4 * 2) = make_uint2(*(uint32_t*)&h0, *(uint32_t*)&h1);
    }
    __syncthreads();

    uint32_t aBase = smem_u32(Ash);
    uint32_t bBase = smem_u32(Bsh);
    float acc[2][2][4] = {};
    #pragma unroll
    for (int ks = 0; ks < 6; ks++) {
        uint32_t af[2][4];
        #pragma unroll
        for (int mi = 0; mi < 2; mi++)
            LDSM_X4(af[mi][0], af[mi][1], af[mi][2], af[mi][3],
                    aBase + (wm * 32 + mi * 16 + rA8) * 208 + ks * 32 + aOff);
        uint32_t rowAddr = bBase + (uint32_t)((ks * 16 + (lane & 15)) * (QK_LDB2 * 4));
        #pragma unroll
        for (int ni = 0; ni < 2; ni++) {
            int cb = (wn * 16 + ni * 8) * 2;
            uint32_t b0, b1;
            asm volatile("ldmatrix.sync.aligned.m8n8.x2.trans.shared.b16 {%0,%1},[%2];"
                         : "=r"(b0), "=r"(b1) : "r"(rowAddr + cb));
            #pragma unroll
            for (int mi = 0; mi < 2; mi++)
                MMA_F16(acc[mi][ni], af[mi][0], af[mi][1], af[mi][2], af[mi][3], b0, b1);
        }
    }

    #pragma unroll
    for (int mi = 0; mi < 2; mi++) {
        int r = m0 + wm * 32 + mi * 16 + lr;
        #pragma unroll
        for (int ni = 0; ni < 2; ni++) {
            int c = n0 + wn * 16 + ni * 8 + lc * 2;
            *(__half2*)(C + (long)r * ldc + c) =
                __floats2half2_rn(acc[mi][ni][0] * scale, acc[mi][ni][1] * scale);
            *(__half2*)(C + (long)(r + 8) * ldc + c) =
                __floats2half2_rn(acc[mi][ni][2] * scale, acc[mi][ni][3] * scale);
        }
    }
}

// ---------------- K3: attention via fp16 mma, non-safe softmax (round-13 proven) ----------------
#define ATT_QKH 0
#define ATT_PN0 24832
#define ATT_PN1 49664
#define ATT_RED 74496
#define ATT_PROB 78592
#define ATT_LS  79424
#define ATT_QB  79552
#define ATTN_SMEM 79616

__global__ void __launch_bounds__(256, 2) attn_mma_kernel(
    const float* __restrict__ patches, const float* __restrict__ bk)
{
    extern __shared__ char sm[];
    uint32_t* qkhU = (uint32_t*)(sm + ATT_QKH);
    float* redS = (float*)(sm + ATT_RED);
    uint32_t* phU = (uint32_t*)(sm + ATT_PROB);
    float* lS = (float*)(sm + ATT_LS);
    float* qbS = (float*)(sm + ATT_QB);

    int b = blockIdx.x, tid = threadIdx.x;
    int lane = tid & 31, wid = tid >> 5;
    int lr = lane >> 2, lc = lane & 3;
    uint32_t smBase = smem_u32(sm);
    int gq = lane >> 3;
    uint32_t rA8 = (gq & 1) * 8 + (lane & 7), aOff = (gq >> 1) * 16;
    uint32_t rB8 = (gq >> 1) * 8 + (lane & 7), bOff = (gq & 1) * 16;

    {
        const uint4* qsrc = (const uint4*)(g_qk_h + (long)b * NHEAD * CH);
        #pragma unroll
        for (int j = 0; j < 3; j++) {
            int f = tid + 256 * j;
            int r = f / 96, c16 = f % 96;
            *(uint4*)(qkhU + r * 388 + c16 * 4) = qsrc[f];
        }
        for (int i = tid; i < 8 * 388; i += 256) qkhU[8 * 388 + i] = 0;
        for (int i = tid; i < 192; i += 256) phU[i] = 0;
        if (tid < 8) lS[tid] = 0.f;
        float s = 0.f;
        #pragma unroll
        for (int j = 0; j < 3; j++) {
            int d = lane + 32 * j;
            s += g_q[b * CH + wid * HD + d] * bk[wid * HD + d];
        }
        #pragma unroll
        for (int o = 16; o > 0; o >>= 1) s += __shfl_xor_sync(0xffffffffu, s, o);
        if (lane == 0) qbS[wid] = s * SCALE;
    }

    int lrow = tid >> 4, lcol = tid & 15;
    const float4* pb4 = (const float4*)(patches + (long)b * NPATCH * CH);
    uint32_t stg[24];

    auto ldg_tile = [&](int t) {
        const float4* src = pb4 + (long)(16 * t + lrow) * 192 + lcol;
        #pragma unroll
        for (int j = 0; j < 12; j++) {
            float4 v = src[16 * j];
            __half2 h0 = __floats2half2_rn(v.x, v.y);
            __half2 h1 = __floats2half2_rn(v.z, v.w);
            stg[2 * j] = *(uint32_t*)&h0; stg[2 * j + 1] = *(uint32_t*)&h1;
        }
    };
    auto sts_tile = [&](int buf) {
        uint32_t* dst = (uint32_t*)(sm + (buf ? ATT_PN1 : ATT_PN0)) + lrow * 388 + lcol * 2;
        #pragma unroll
        for (int j = 0; j < 12; j++)
            *(uint2*)(dst + 32 * j) = make_uint2(stg[2 * j], stg[2 * j + 1]);
    };

    ldg_tile(0);
    sts_tile(0);
    __syncthreads();

    float ctx[12][4] = {};
    uint32_t qkhAddr = smBase + ATT_QKH;
    uint32_t kwB = wid * 192;

    for (int t = 0; t < 16; t++) {
        int buf = t & 1;
        uint32_t pnAddr = smBase + (buf ? ATT_PN1 : ATT_PN0);

        if (t < 15) ldg_tile(t + 1);

        float lgC[2][4] = {};
        #pragma unroll
        for (int ks = 0; ks < 6; ks++) {
            uint32_t a0, a1, a2, a3;
            LDSM_X4(a0, a1, a2, a3, qkhAddr + rA8 * 1552 + kwB + ks * 32 + aOff);
            uint32_t b0, b1, b2, b3;
            LDSM_X4(b0, b1, b2, b3, pnAddr + rB8 * 1552 + kwB + ks * 32 + bOff);
            MMA_F16(lgC[0], a0, a1, a2, a3, b0, b1);
            MMA_F16(lgC[1], a0, a1, a2, a3, b2, b3);
        }
        {
            float* rw = redS + wid * 128;
            #pragma unroll
            for (int nc = 0; nc < 2; nc++)
                *(float2*)(rw + lr * 16 + nc * 8 + 2 * lc) = make_float2(lgC[nc][0], lgC[nc][1]);
        }
        __syncthreads();

        if (tid < 128) {
            int h = tid >> 4, n = tid & 15;
            float lg = qbS[h];
            #pragma unroll
            for (int w = 0; w < 8; w++) lg += redS[w * 128 + h * 16 + n];
            float p = __expf(lg);
            float ps = p;
            #pragma unroll
            for (int o = 8; o > 0; o >>= 1) ps += __shfl_xor_sync(0xffffffffu, ps, o);
            if (n == 0) lS[h] += ps;
            ((__half*)phU)[h * 24 + n] = __float2half(p);
        }
        __syncthreads();

        {
            uint32_t pa0 = phU[lr * 12 + lc];
            uint32_t pa1 = phU[(lr + 8) * 12 + lc];
            uint32_t pa2 = phU[lr * 12 + lc + 4];
            uint32_t pa3 = phU[(lr + 8) * 12 + lc + 4];
            uint32_t rowAddr = pnAddr + (lane & 15) * 1552;
            #pragma unroll
            for (int j = 0; j < 12; j++) {
                int ch = wid * 96 + 8 * j;
                uint32_t b0, b1;
                asm volatile("ldmatrix.sync.aligned.m8n8.x2.trans.shared.b16 {%0,%1},[%2];"
                             : "=r"(b0), "=r"(b1) : "r"(rowAddr + ch * 2));
                MMA_F16(ctx[j], pa0, pa1, pa2, pa3, b0, b1);
            }
        }
        if (t < 15) sts_tile(buf ^ 1);
        __syncthreads();
    }

    {
        float inv = 1.f / lS[lr];
        #pragma unroll
        for (int j = 0; j < 12; j++) {
            int ch = wid * 96 + 8 * j + 2 * lc;
            *(float2*)(g_ctx + ((long)b * 8 + lr) * CH + ch) =
                make_float2(ctx[j][0] * inv, ctx[j][1] * inv);
        }
    }
}

// ---------------- K5: attr_in + gating + router, warp per token ----------------
__global__ void __launch_bounds__(256) attr_gate_warp(
    const float* __restrict__ prompt, const float* __restrict__ vcls,
    const float* __restrict__ gate_w, const float* __restrict__ gate_b,
    const float* __restrict__ r1_w, const float* __restrict__ r1_b)
{
    int warp = (blockIdx.x * 256 + threadIdx.x) >> 5;
    int lane = threadIdx.x & 31;
    int b = warp / NATTR, a = warp % NATTR;

    float x[24];
    float part[5] = {};
    #pragma unroll
    for (int j = 0; j < 12; j++) {
        int c = lane * 2 + 64 * j;
        float2 mi = *(const float2*)&g_moe_in[b * CH + c];
        float2 pr = *(const float2*)&prompt[a * CH + c];
        float2 vc = *(const float2*)&vcls[b * CH + c];
        float x0 = mi.x + pr.x + vc.x;
        float x1 = mi.y + pr.y + vc.y;
        x[2 * j] = x0; x[2 * j + 1] = x1;
        #pragma unroll
        for (int e = 0; e < 4; e++) {
            float2 gw = *(const float2*)&gate_w[e * CH + c];
            part[e] += x0 * gw.x + x1 * gw.y;
        }
        float2 r1 = *(const float2*)&r1_w[c];
        part[4] += x0 * r1.x + x1 * r1.y;
    }
    #pragma unroll
    for (int o = 16; o > 0; o >>= 1)
        #pragma unroll
        for (int e = 0; e < 5; e++) part[e] += __shfl_xor_sync(0xffffffffu, part[e], o);

    float g[4];
    #pragma unroll
    for (int e = 0; e < 4; e++) g[e] = part[e] + gate_b[e];
    float v0 = g[0], v1 = g[1], v2 = g[2], v3 = g[3], t;
    if (v0 < v1) { t = v0; v0 = v1; v1 = t; }
    if (v2 < v3) { t = v2; v2 = v3; v3 = t; }
    if (v0 < v2) { t = v0; v0 = v2; v2 = t; }
    if (v1 < v3) { t = v1; v1 = v3; v3 = t; }
    if (v1 < v2) { t = v1; v1 = v2; v2 = t; }
    float thr = v2, mx = v0;
    float s = 0.f, w[4];
    #pragma unroll
    for (int e = 0; e < 4; e++) {
        w[e] = (g[e] >= thr) ? __expf(g[e] - mx) : 0.f;
        s += w[e];
    }
    float inv = 1.f / s;
    if (lane == 0) {
        *(float4*)&g_wgt[warp * 4] = make_float4(w[0] * inv, w[1] * inv, w[2] * inv, w[3] * inv);
        float hv = part[4] + r1_b[0];
        float x3 = hv * hv * hv;
        float gl = 0.5f * hv * (1.f + tanhf(0.7978845608028654f * (hv + 0.044715f * x3)));
        g_scores[warp] = gl * g_r2m[0] + g_r2m[1];
    }

    __half* dst = g_attr_h + (long)warp * CH;
    #pragma unroll
    for (int j = 0; j < 12; j++) {
        int c = lane * 2 + 64 * j;
        *(__half2*)&dst[c] = __floats2half2_rn(x[2 * j], x[2 * j + 1]);
    }
}

// ---------------- K6: expert GEMM, split over expert pairs (z in {0,1}) ----------------
// z handles experts {2z, 2z+1}: 48 K-steps, writes weighted partial (+ its rank-2 bias
// term) to g_moe_out half z. final_kernel sums halves.
__global__ void __launch_bounds__(256) expert_fp16_kernel(const float* __restrict__ exp_b) {
    __shared__ float ebS[512];
    __shared__ float wS[512];
    __shared__ __align__(16) __half Ah[2][128 * LDH];
    __shared__ __align__(16) __half Bh[2][128 * LDH];

    int m0c = blockIdx.x * 128, n0c = blockIdx.y * 128;
    int eg = blockIdx.z;                      // expert group: experts 2eg, 2eg+1
    int tid = threadIdx.x;
    int lane = tid & 31, wid = tid >> 5;
    int wm = wid & 1, wn = wid >> 1;
    int kv = tid & 3, rb = tid >> 2;

    int gq = lane >> 3;
    uint32_t rA8 = (gq & 1) * 8 + (lane & 7), aOff = (gq >> 1) * 16;
    uint32_t rB8 = (gq >> 1) * 8 + (lane & 7), bOff = (gq & 1) * 16;
    uint32_t AhA[2] = { smem_u32(&Ah[0][0]), smem_u32(&Ah[1][0]) };
    uint32_t BhA[2] = { smem_u32(&Bh[0][0]), smem_u32(&Bh[1][0]) };

    for (int i = tid; i < 512; i += 256) {
        int e = (i >> 7);                     // 0..3 local; map to global expert
        ebS[i] = exp_b[((eg << 1) + (e >> 1)) * CH + n0c + (i & 127)];  // only halves 0,1 used
        wS[i]  = g_wgt[(m0c + (i >> 2)) * 4 + (i & 3)];
    }

    uint4 uA[2], uB[2];
    auto do_ldg = [&](int s) {
        int e = (eg << 1) + s / 24, k0 = (s % 24) * 32;
        const __half* ap = g_attr_h + (long)(m0c + rb) * CH + k0 + kv * 8;
        const __half* bp = g_expw_h + (long)e * CH * CH + (long)(n0c + rb) * CH + k0 + kv * 8;
        #pragma unroll
        for (int i = 0; i < 2; i++) {
            uA[i] = *(const uint4*)(ap + (long)(64 * i) * CH);
            uB[i] = *(const uint4*)(bp + (long)(64 * i) * CH);
        }
    };
    auto do_sts = [&](int buf, int s) {
        int e = (eg << 1) + s / 24;
        #pragma unroll
        for (int i = 0; i < 2; i++) {
            int mr = rb + 64 * i;
            __half2 hw = __float2half2_rn(wS[mr * 4 + e]);
            uint4 u = uA[i];
            __half2* h2 = (__half2*)&u;
            h2[0] = __hmul2(h2[0], hw); h2[1] = __hmul2(h2[1], hw);
            h2[2] = __hmul2(h2[2], hw); h2[3] = __hmul2(h2[3], hw);
            *(uint4*)&Ah[buf][mr * LDH + kv * 8] = u;
            *(uint4*)&Bh[buf][mr * LDH + kv * 8] = uB[i];
        }
    };

    do_ldg(0);
    __syncthreads();            // wS ready
    do_sts(0, 0);
    do_ldg(1);
    __syncthreads();

    int lr = lane >> 2, lc = lane & 3;
    float acc[4][4][4] = {};
    for (int s = 0; s < 48; s++) {
        int buf = s & 1;
        #pragma unroll
        for (int kk = 0; kk < 2; kk++) {
            uint32_t af[4][4];
            #pragma unroll
            for (int mi = 0; mi < 4; mi++)
                LDSM_X4(af[mi][0], af[mi][1], af[mi][2], af[mi][3],
                        AhA[buf] + (wm * 64 + mi * 16 + rA8) * 80 + kk * 32 + aOff);
            uint32_t bf[4][2];
            #pragma unroll
            for (int p = 0; p < 2; p++)
                LDSM_X4(bf[2 * p][0], bf[2 * p][1], bf[2 * p + 1][0], bf[2 * p + 1][1],
                        BhA[buf] + (wn * 32 + p * 16 + rB8) * 80 + kk * 32 + bOff);
            #pragma unroll
            for (int mi = 0; mi < 4; mi++)
                #pragma unroll
                for (int ni = 0; ni < 4; ni++)
                    MMA_F16(acc[mi][ni], af[mi][0], af[mi][1], af[mi][2], af[mi][3],
                            bf[ni][0], bf[ni][1]);
        }
        if (s < 47) do_sts(buf ^ 1, s + 1);
        if (s < 46) do_ldg(s + 2);
        __syncthreads();
    }

    float* outHalf = g_moe_out + (long)eg * NTOK * CH;
    #pragma unroll
    for (int mi = 0; mi < 4; mi++) {
        int r0 = wm * 64 + mi * 16 + lr;
        float4 w0 = *(const float4*)&wS[r0 * 4];
        float4 w1 = *(const float4*)&wS[(r0 + 8) * 4];
        float we0a = eg ? w0.z : w0.x, we1a = eg ? w0.w : w0.y;
        float we0b = eg ? w1.z : w1.x, we1b = eg ? w1.w : w1.y;
        #pragma unroll
        for (int ni = 0; ni < 4; ni++) {
            int c = wn * 32 + ni * 8 + lc * 2;
            float e0 = ebS[c],       f0 = ebS[c + 1];     // bias of expert 2eg
            float e1 = ebS[128 + c], f1 = ebS[129 + c];   // bias of expert 2eg+1
            float b00 = we0a * e0 + we1a * e1;
            float b01 = we0a * f0 + we1a * f1;
            float b10 = we0b * e0 + we1b * e1;
            float b11 = we0b * f0 + we1b * f1;
            *(float2*)(outHalf + (size_t)(m0c + r0) * CH + n0c + c) =
                make_float2(acc[mi][ni][0] + b00, acc[mi][ni][1] + b01);
            *(float2*)(outHalf + (size_t)(m0c + r0 + 8) * CH + n0c + c) =
                make_float2(acc[mi][ni][2] + b10, acc[mi][ni][3] + b11);
        }
    }
}

// ---------------- K7: top-7-of-10 attrs, softmax combine over the two halves ----------------
__global__ void final_kernel(float* __restrict__ out) {
    int b = blockIdx.x, tid = threadIdx.x;
    __shared__ float wts[7];
    __shared__ int idx[7];
    if (tid == 0) {
        float sc[10];
        for (int a = 0; a < 10; a++) sc[a] = g_scores[b * 10 + a];
        bool used[10] = {};
        float vs[7];
        for (int k = 0; k < 7; k++) {
            int bi = 0; float bv = -3.4e38f;
            for (int a = 0; a < 10; a++) {
                if (!used[a] && sc[a] > bv) { bv = sc[a]; bi = a; }
            }
            used[bi] = true; vs[k] = bv; idx[k] = bi;
        }
        float mx = vs[0], s = 0.f;
        for (int k = 0; k < 7; k++) { vs[k] = __expf(vs[k] - mx); s += vs[k]; }
        float inv = 1.f / s;
        for (int k = 0; k < 7; k++) wts[k] = vs[k] * inv;
    }
    __syncthreads();
    #pragma unroll
    for (int j = 0; j < 3; j++) {
        int c = tid + j * 256;
        float s = 0.f;
        #pragma unroll
        for (int k = 0; k < 7; k++) {
            long base = ((long)b * 10 + idx[k]) * CH + c;
            s += wts[k] * (g_moe_out[base] + g_moe_out[(long)NTOK * CH + base]);
        }
        out[b * CH + c] = s;
    }
}

// ---------------- host ----------------
extern "C" void kernel_launch(void* const* d_in, const int* in_sizes, int n_in,
                              void* d_out, int out_size) {
    const float* text_cls = (const float*)d_in[0];
    const float* visual_cls = (const float*)d_in[1];
    const float* patches = (const float*)d_in[2];
    const float* prompt = (const float*)d_in[3];
    const float* Wq = (const float*)d_in[4];  const float* bq = (const float*)d_in[5];
    const float* Wk = (const float*)d_in[6];  const float* bk = (const float*)d_in[7];
    const float* Wv = (const float*)d_in[8];  const float* bv = (const float*)d_in[9];
    const float* Wo = (const float*)d_in[10]; const float* bo = (const float*)d_in[11];
    const float* gate_w = (const float*)d_in[12]; const float* gate_b = (const float*)d_in[13];
    const float* exp_w = (const float*)d_in[14];  const float* exp_b = (const float*)d_in[15];
    const float* r1_w = (const float*)d_in[16];   const float* r1_b = (const float*)d_in[17];
    const float* r2_w = (const float*)d_in[18];   const float* r2_b = (const float*)d_in[19];
    float* out = (float*)d_out;

    (void)in_sizes; (void)n_in; (void)out_size;

    float *p_q, *p_ctx, *p_o, *p_moe_in;
    __half* p_qkh;
    cudaGetSymbolAddress((void**)&p_q, g_q);
    cudaGetSymbolAddress((void**)&p_qkh, g_qk_h);
    cudaGetSymbolAddress((void**)&p_ctx, g_ctx);
    cudaGetSymbolAddress((void**)&p_o, g_o);
    cudaGetSymbolAddress((void**)&p_moe_in, g_moe_in);

    cudaFuncSetAttribute(attn_mma_kernel, cudaFuncAttributeMaxDynamicSharedMemorySize, ATTN_SMEM);

    expw_cvt_r2<<<577, 256>>>(exp_w, r2_w, r2_b);
    // q = text_cls @ Wq^T + bq
    gemm_abt_f16<<<dim3(4, 12, 1), 256>>>(text_cls, CH, 0, Wq, CH, 0, bq, 0,
                                          p_q, CH, 0, CH, CH);
    // qk fold (fp16 out): per head h, qk_h = SCALE * (q_h @ Wk[h*96:(h+1)*96, :])
    gemm_ab_f16<<<dim3(4, 12, 8), 256>>>(p_q, CH, HD,
                                         Wk, CH, HD,
                                         p_qkh, NHEAD * CH, CH, SCALE);
    attn_mma_kernel<<<BATCH, 256, ATTN_SMEM>>>(patches, bk);
    // o slice: ctx_h @ Wv_h^T + bv_h
    gemm_abt_f16<<<dim3(4, 2, 8), 256>>>(p_ctx, NHEAD * CH, CH,
                                         Wv, CH, (long)HD * CH,
                                         bv, HD,
                                         p_o, CH, HD, HD, CH);
    // moe_in = o @ Wo^T + bo
    gemm_abt_f16<<<dim3(4, 12, 1), 256>>>(p_o, CH, 0, Wo, CH, 0, bo, 0,
                                          p_moe_in, CH, 0, CH, CH);
    attr_gate_warp<<<320, 256>>>(prompt, visual_cls, gate_w, gate_b, r1_w, r1_b);
    // expert GEMM split over expert pairs: 240 CTAs
    expert_fp16_kernel<<<dim3(20, 6, 2), 256>>>(exp_b);
    final_kernel<<<BATCH, 256>>>(out);
}